// round 13
// baseline (speedup 1.0000x reference)
#include <cuda_runtime.h>
#include <cuda_fp16.h>
#include <math.h>
#include <stdint.h>

#define T_TOK 32768
#define C_DIM 768
#define E_NUM 4
#define HD_DIM 192
#define KB 64                            // 64 halfs per k-iter (128B rows)
#define A_STG 16384                      // A tile bytes (128 rows x 128B)
#define STG_MAX 49152                    // stage stride: A 16KB + B(max 256 rows) 32KB
#define TBL_OFF (3 * STG_MAX)
#define SMEM_TOT (TBL_OFF + 3072 + 512 + 128)

__device__ float  g_combine[T_TOK * E_NUM];
__device__ int    g_cnt[8];
__device__ int    g_item;
__device__ int    g_fin;
__device__ int    g_done[8];
__device__ int    g_bucket[6 * T_TOK];
__device__ __half g_xh[(size_t)T_TOK * C_DIM];
__device__ __half g_hmid[(size_t)T_TOK * 384];
__device__ __half g_w1h[E_NUM * HD_DIM * C_DIM];
__device__ __half g_w2h[E_NUM * C_DIM * HD_DIM];

__constant__ int c_pairs[6][2] = {{0,1},{0,2},{0,3},{1,2},{1,3},{2,3}};

// ---------------- helpers ----------------
__device__ __forceinline__ uint32_t smem_u32(const void* p) {
    uint32_t a;
    asm("{ .reg .u64 t; cvta.to.shared.u64 t, %1; cvt.u32.u64 %0, t; }" : "=r"(a) : "l"(p));
    return a;
}
#define CPA(s, g)  asm volatile("cp.async.cg.shared.global [%0], [%1], 16;" :: "r"(s), "l"(g))
#define CPC()      asm volatile("cp.async.commit_group;" ::: "memory")
#define CPW(n)     asm volatile("cp.async.wait_group %0;" :: "n"(n) : "memory")

#define LDSM4(r0, r1, r2, r3, addr)                                                     \
    asm volatile("ldmatrix.sync.aligned.m8n8.x4.shared.b16 {%0,%1,%2,%3}, [%4];"        \
                 : "=r"(r0), "=r"(r1), "=r"(r2), "=r"(r3) : "r"(addr))

#define MMA16(c, a, b)                                                                  \
    asm volatile("mma.sync.aligned.m16n8k16.row.col.f32.f16.f16.f32 "                   \
                 "{%0,%1,%2,%3},{%4,%5,%6,%7},{%8,%9},{%0,%1,%2,%3};"                   \
                 : "+f"((c)[0]), "+f"((c)[1]), "+f"((c)[2]), "+f"((c)[3])               \
                 : "r"((a)[0]), "r"((a)[1]), "r"((a)[2]), "r"((a)[3]),                  \
                   "r"((b)[0]), "r"((b)[1]))

template <int NCH>
__device__ __forceinline__ void ld_tile_p(uint32_t sbase, const uint64_t* __restrict__ rp,
                                          uint32_t koff, int tid) {
    #pragma unroll
    for (int c = tid; c < NCH; c += 256) {
        int row = c >> 3, ch = c & 7;
        const char* gp = (const char*)(rp[row] + koff) + ch * 16;
        uint32_t off = (uint32_t)(row * 128 + ((ch ^ (row & 7)) << 4));
        CPA(sbase + off, gp);
    }
}

// ---------------------------------------------------------------------------
// Router: 2 tokens per warp; weight conversion; fused bucketize.
// ---------------------------------------------------------------------------
__global__ __launch_bounds__(256) void router_kernel(
    const float* __restrict__ x, const float* __restrict__ rw, const float* __restrict__ rb,
    const float* __restrict__ w1, const float* __restrict__ w2)
{
    __shared__ int s_pair[16];
    {
        const int N1 = E_NUM * HD_DIM * C_DIM;
        for (int i = blockIdx.x * 256 + threadIdx.x; i < N1; i += gridDim.x * 256) {
            g_w1h[i] = __float2half_rn(w1[i]);
            g_w2h[i] = __float2half_rn(w2[i]);
        }
    }
    const int warp = threadIdx.x >> 5, lane = threadIdx.x & 31;
    const int t0 = blockIdx.x * 16 + warp * 2;
    const float* xr0 = x + (size_t)t0 * C_DIM;
    const float* xr1 = xr0 + C_DIM;
    __half* xo0 = g_xh + (size_t)t0 * C_DIM;
    __half* xo1 = xo0 + C_DIM;

    float a0[4] = {0.f, 0.f, 0.f, 0.f};
    float a1[4] = {0.f, 0.f, 0.f, 0.f};
    for (int c = lane * 4; c < C_DIM; c += 128) {
        float4 x0 = *(const float4*)(xr0 + c);
        float4 x1 = *(const float4*)(xr1 + c);
        #pragma unroll
        for (int e = 0; e < 4; e++) {
            float4 wv = *(const float4*)(rw + e * C_DIM + c);
            a0[e] += x0.x*wv.x + x0.y*wv.y + x0.z*wv.z + x0.w*wv.w;
            a1[e] += x1.x*wv.x + x1.y*wv.y + x1.z*wv.z + x1.w*wv.w;
        }
        __half2 h0 = __floats2half2_rn(x0.x, x0.y);
        __half2 h1 = __floats2half2_rn(x0.z, x0.w);
        *(uint2*)(xo0 + c) = make_uint2(*(uint32_t*)&h0, *(uint32_t*)&h1);
        __half2 h2 = __floats2half2_rn(x1.x, x1.y);
        __half2 h3 = __floats2half2_rn(x1.z, x1.w);
        *(uint2*)(xo1 + c) = make_uint2(*(uint32_t*)&h2, *(uint32_t*)&h3);
    }
    #pragma unroll
    for (int o = 16; o > 0; o >>= 1) {
        #pragma unroll
        for (int e = 0; e < 4; e++) {
            a0[e] += __shfl_xor_sync(0xffffffffu, a0[e], o);
            a1[e] += __shfl_xor_sync(0xffffffffu, a1[e], o);
        }
    }
    if (lane < 2) {
        const float* av = (lane == 0) ? a0 : a1;
        const int t = t0 + lane;
        float l[4];
        #pragma unroll
        for (int e = 0; e < 4; e++) l[e] = av[e] + rb[e];
        float mx = fmaxf(fmaxf(l[0], l[1]), fmaxf(l[2], l[3]));
        float p[4]; float Z = 0.f;
        #pragma unroll
        for (int e = 0; e < 4; e++) { p[e] = expf(l[e] - mx); Z += p[e]; }
        #pragma unroll
        for (int e = 0; e < 4; e++) p[e] /= Z;
        int i0 = 0;
        #pragma unroll
        for (int e = 1; e < 4; e++) if (p[e] > p[i0]) i0 = e;
        int i1 = (i0 == 0) ? 1 : 0;
        #pragma unroll
        for (int e = 0; e < 4; e++) if (e != i0 && p[e] > p[i1]) i1 = e;
        float s = p[i0] + p[i1] + 1e-8f;
        float ov[4] = {0.f, 0.f, 0.f, 0.f};
        ov[i0] = p[i0] / s; ov[i1] = p[i1] / s;
        ((float4*)g_combine)[t] = make_float4(ov[0], ov[1], ov[2], ov[3]);
        int lo = min(i0, i1), hi = max(i0, i1);
        s_pair[warp * 2 + lane] = (lo == 0) ? hi - 1 : ((lo == 1) ? hi + 1 : 5);
    }
    __syncthreads();
    if (threadIdx.x < 16) {
        int pid = s_pair[threadIdx.x];
        unsigned mask = __match_any_sync(0x0000ffffu, pid) & 0xffffu;
        int leader = __ffs(mask) - 1;
        int rank = __popc(mask & ((1u << threadIdx.x) - 1));
        int base = 0;
        if (threadIdx.x == leader) base = atomicAdd(&g_cnt[pid], __popc(mask));
        base = __shfl_sync(0x0000ffffu, base, leader);
        g_bucket[pid * T_TOK + base + rank] = blockIdx.x * 16 + threadIdx.x;
    }
}

// ---------------------------------------------------------------------------
// One GEMM tile. MODE 1 (fc1): 128 x 192 (NJ=6). MODE 2 (fc2): 128 x 256 (NJ=8).
// Warp grid 2(m) x 4(n); warp tile 64 x (NJ*8).
// ---------------------------------------------------------------------------
template <int MODE>
__device__ __forceinline__ void gemm_item(
    int b, int cnt, int m0, int n0,
    const float* __restrict__ bias, float* __restrict__ outp,
    char* smc, uint32_t sb)
{
    constexpr int NJ  = (MODE == 1) ? 6 : 8;        // n8 tiles per warp
    constexpr int NBT = NJ * 32;                    // CTA n-tile: 192 / 256
    constexpr int NKI = (MODE == 1) ? (C_DIM / KB) : (384 / KB);   // 12 / 6
    constexpr int BCH = NBT * 8;                    // B 16B chunks per stage

    uint64_t* rpA = (uint64_t*)(smc + TBL_OFF);     // 128 entries
    uint64_t* rpB = rpA + 128;                      // up to 256 entries
    int* stok = (int*)(rpB + 256);
    const int e0 = c_pairs[b][0], e1 = c_pairs[b][1];

    const int tid = threadIdx.x, lane = tid & 31, w = tid >> 5;
    const int wm = w & 1, wn = w >> 1;
    const int lq = lane >> 2, lr = lane & 3;
    const int ph = w & 3;

    if (tid < 128) {
        int p = m0 + tid;
        int t = g_bucket[b * T_TOK + (p < cnt ? p : m0)];
        stok[tid] = t;
        rpA[tid] = (MODE == 1)
            ? (uint64_t)(const char*)(g_xh + (size_t)t * C_DIM)
            : (uint64_t)(const char*)(g_hmid + (size_t)t * 384);
    }
    for (int row = tid; row < NBT; row += 256) {
        if (MODE == 1) {
            int n = n0 + row;
            int e = (n < HD_DIM) ? e0 : e1;
            int h = (n < HD_DIM) ? n : n - HD_DIM;
            rpB[row] = (uint64_t)(const char*)(g_w1h + ((size_t)e * HD_DIM + h) * C_DIM);
        } else {
            rpB[row] = (uint64_t)(const char*)(g_w2h + (size_t)(n0 + row) * HD_DIM);
        }
    }
    __syncthreads();

    auto koffB = [&](int i) -> uint32_t {
        if (MODE == 1) return (uint32_t)(i * 128);
        int e = i / 3;
        int h0 = (i - e * 3) * KB;
        return (uint32_t)(((e == 0) ? e0 : e1) * C_DIM * HD_DIM + h0) * 2u;
    };

    const int ms = lane >> 3, rl = lane & 7;
    const int a_ms2 = ms >> 1;
    const int b_ms1 = ms & 1;
    uint32_t a_rowoff[4], b_rowoff[NJ / 2];
    #pragma unroll
    for (int mi = 0; mi < 4; mi++)
        a_rowoff[mi] = (uint32_t)((wm * 64 + mi * 16 + (ms & 1) * 8 + rl) * 128);
    #pragma unroll
    for (int p = 0; p < NJ / 2; p++)
        b_rowoff[p] = (uint32_t)((wn * (NJ * 8) + p * 16 + (ms >> 1) * 8 + rl) * 128);

    float acc[4][NJ][4] = {};

    #pragma unroll
    for (int p = 0; p < 2; p++) {
        ld_tile_p<1024>(sb + p * STG_MAX, rpA, (uint32_t)(p * 128), tid);
        ld_tile_p<BCH>(sb + p * STG_MAX + A_STG, rpB, koffB(p), tid);
        CPC();
    }

    for (int i = 0; i < NKI; i++) {
        if (i < NKI - 1) { CPW(1); } else { CPW(0); }
        __syncthreads();
        if (i + 2 < NKI) {
            const int s2 = (i + 2) % 3;
            ld_tile_p<1024>(sb + s2 * STG_MAX, rpA, (uint32_t)((i + 2) * 128), tid);
            ld_tile_p<BCH>(sb + s2 * STG_MAX + A_STG, rpB, koffB(i + 2), tid);
            CPC();
        }
        const uint32_t smA = sb + (i % 3) * STG_MAX;
        const uint32_t smB = smA + A_STG;

        #pragma unroll
        for (int kks = 0; kks < 4; kks++) {
            const int kk = (kks + ph) & 3;
            uint32_t a[4][4], bb[NJ][2];
            const uint32_t koA = (uint32_t)(((2 * kk + a_ms2) ^ rl) << 4);
            const uint32_t koB = (uint32_t)(((2 * kk + b_ms1) ^ rl) << 4);
            #pragma unroll
            for (int mi = 0; mi < 4; mi++)
                LDSM4(a[mi][0], a[mi][1], a[mi][2], a[mi][3], smA + a_rowoff[mi] + koA);
            #pragma unroll
            for (int p = 0; p < NJ / 2; p++)
                LDSM4(bb[2*p][0], bb[2*p][1], bb[2*p+1][0], bb[2*p+1][1],
                      smB + b_rowoff[p] + koB);
            #pragma unroll
            for (int mi = 0; mi < 4; mi++)
                #pragma unroll
                for (int nj = 0; nj < NJ; nj++)
                    MMA16(acc[mi][nj], a[mi], bb[nj]);
        }
    }

    #pragma unroll
    for (int mi = 0; mi < 4; mi++) {
        #pragma unroll
        for (int half = 0; half < 2; half++) {
            const int rloc = wm * 64 + mi * 16 + lq + half * 8;
            if (m0 + rloc >= cnt) continue;
            const int t = stok[rloc];
            if (MODE == 1) {
                __half* orow = g_hmid + (size_t)t * 384;
                #pragma unroll
                for (int nj = 0; nj < NJ; nj++) {
                    const int n = n0 + wn * (NJ * 8) + nj * 8 + lr * 2;
                    const int e = (n < HD_DIM) ? e0 : e1;
                    const int h = (n < HD_DIM) ? n : n - HD_DIM;
                    const float cw = g_combine[t * 4 + e];
                    float vv[2];
                    #pragma unroll
                    for (int u = 0; u < 2; u++) {
                        float d = acc[mi][nj][half * 2 + u] + __ldg(&bias[e * HD_DIM + h + u]);
                        float g = 0.5f * d * (1.0f + erff(d * 0.70710678118654752f));
                        vv[u] = g * cw;
                    }
                    __half2 hv = __floats2half2_rn(vv[0], vv[1]);
                    *(__half2*)(orow + n) = hv;
                }
            } else {
                const float4 cw = ((const float4*)g_combine)[t];
                float* orow = outp + (size_t)t * C_DIM;
                #pragma unroll
                for (int nj = 0; nj < NJ; nj++) {
                    const int n = n0 + wn * (NJ * 8) + nj * 8 + lr * 2;
                    float2 v;
                    #pragma unroll
                    for (int u = 0; u < 2; u++) {
                        const int c = n + u;
                        float bv = cw.x * __ldg(&bias[0 * C_DIM + c])
                                 + cw.y * __ldg(&bias[1 * C_DIM + c])
                                 + cw.z * __ldg(&bias[2 * C_DIM + c])
                                 + cw.w * __ldg(&bias[3 * C_DIM + c]);
                        ((float*)&v)[u] = acc[mi][nj][half * 2 + u] + bv;
                    }
                    *(float2*)(orow + n) = v;
                }
            }
        }
    }
}

// ---------------------------------------------------------------------------
// Persistent fused scheduler: fc1 tiles (192-wide, 2/bucket-row) then fc2
// tiles (256-wide, 3/bucket-row) gated per bucket. Self-resetting.
// ---------------------------------------------------------------------------
__global__ __launch_bounds__(256, 1)
void moe_fused(const float* __restrict__ b1, const float* __restrict__ b2,
               float* __restrict__ outp)
{
    extern __shared__ __align__(128) char smc[];
    const uint32_t sb = smem_u32(smc);
    int* sh_item = (int*)(smc + TBL_OFF + 3072 + 512);
    const int tid = threadIdx.x;

    int cnt_[6], mt_[6];
    int tot1 = 0, tot2 = 0;
    #pragma unroll
    for (int e = 0; e < 6; e++) {
        cnt_[e] = __ldg(&g_cnt[e]);
        mt_[e] = (cnt_[e] + 127) >> 7;
        tot1 += mt_[e] * 2;                 // fc1: 384/192 = 2 n-tiles
        tot2 += mt_[e] * 3;                 // fc2: 768/256 = 3 n-tiles
    }
    const int TOT = tot1 + tot2;

    while (true) {
        if (tid == 0) *sh_item = atomicAdd(&g_item, 1);
        __syncthreads();
        const int item = *sh_item;
        __syncthreads();
        if (item >= TOT) break;

        int b = 0, mt = 0, nt = 0, mode;
        if (item < tot1) {
            mode = 1;
            int it = item;
            #pragma unroll
            for (int e = 0; e < 6; e++) {
                int n = mt_[e] * 2;
                if (it < n) { b = e; mt = it >> 1; nt = it & 1; break; }
                it -= n;
            }
        } else {
            mode = 2;
            int it = item - tot1;
            #pragma unroll
            for (int e = 0; e < 6; e++) {
                int n = mt_[e] * 3;
                if (it < n) { b = e; mt = it / 3; nt = it % 3; break; }
                it -= n;
            }
            if (tid == 0) {
                const int need = mt_[b] * 2;
                while (*(volatile int*)&g_done[b] < need) { }
            }
        }

        if (mode == 1)
            gemm_item<1>(b, cnt_[b], mt * 128, nt * 192, b1, nullptr, smc, sb);
        else
            gemm_item<2>(b, cnt_[b], mt * 128, nt * 256, b2, outp, smc, sb);

        __syncthreads();
        if (mode == 1 && tid == 0) {
            __threadfence();
            atomicAdd(&g_done[b], 1);
        }
    }

    if (tid == 0) {
        int f = atomicAdd(&g_fin, 1);
        if (f == (int)gridDim.x - 1) {
            #pragma unroll
            for (int e = 0; e < 8; e++) { g_cnt[e] = 0; g_done[e] = 0; }
            g_item = 0;
            g_fin = 0;
            __threadfence();
        }
    }
}

// ---------------------------------------------------------------------------
extern "C" void kernel_launch(void* const* d_in, const int* in_sizes, int n_in,
                              void* d_out, int out_size)
{
    const float* x  = (const float*)d_in[0];
    const float* rw = (const float*)d_in[1];
    const float* rb = (const float*)d_in[2];
    const float* w1 = (const float*)d_in[3];
    const float* b1 = (const float*)d_in[4];
    const float* w2 = (const float*)d_in[5];
    const float* b2 = (const float*)d_in[6];
    float* out = (float*)d_out;

    static int nsm = 0;
    if (nsm == 0) {
        cudaDeviceGetAttribute(&nsm, cudaDevAttrMultiProcessorCount, 0);
        cudaFuncSetAttribute(moe_fused, cudaFuncAttributeMaxDynamicSharedMemorySize, SMEM_TOT);
    }

    router_kernel<<<T_TOK / 16, 256>>>(x, rw, rb, w1, w2);
    moe_fused<<<nsm, 256, SMEM_TOT>>>(b1, b2, out);
}

// round 15
// speedup vs baseline: 1.1825x; 1.1825x over previous
#include <cuda_runtime.h>
#include <cuda_fp16.h>
#include <math.h>
#include <stdint.h>

#define T_TOK 32768
#define C_DIM 768
#define E_NUM 4
#define HD_DIM 192
#define KB 64                           // 64 halfs per k-iter (128B rows)
#define STG_B 32768                     // bytes per stage: A 16KB + B 16KB
#define TBL_OFF (3 * STG_B)
#define TBL_PAR 2560                    // rpA 1024 + rpB 1024 + stok 512
#define SCH_OFF (TBL_OFF + 2 * TBL_PAR)
#define SMEM_TOT (SCH_OFF + 128)

__device__ float  g_combine[T_TOK * E_NUM];
__device__ int    g_cnt[8];
__device__ int    g_item;
__device__ int    g_fin;
__device__ int    g_done[8];
__device__ int    g_bucket[6 * T_TOK];
__device__ __half g_xh[(size_t)T_TOK * C_DIM];
__device__ __half g_hmid[(size_t)T_TOK * 384];
__device__ __half g_w1h[E_NUM * HD_DIM * C_DIM];
__device__ __half g_w2h[E_NUM * C_DIM * HD_DIM];

__constant__ int c_pairs[6][2] = {{0,1},{0,2},{0,3},{1,2},{1,3},{2,3}};

// ---------------- helpers ----------------
__device__ __forceinline__ uint32_t smem_u32(const void* p) {
    uint32_t a;
    asm("{ .reg .u64 t; cvta.to.shared.u64 t, %1; cvt.u32.u64 %0, t; }" : "=r"(a) : "l"(p));
    return a;
}
#define CPA(s, g)  asm volatile("cp.async.cg.shared.global [%0], [%1], 16;" :: "r"(s), "l"(g))
#define CPC()      asm volatile("cp.async.commit_group;" ::: "memory")
#define CPW(n)     asm volatile("cp.async.wait_group %0;" :: "n"(n) : "memory")

#define LDSM4(r0, r1, r2, r3, addr)                                                     \
    asm volatile("ldmatrix.sync.aligned.m8n8.x4.shared.b16 {%0,%1,%2,%3}, [%4];"        \
                 : "=r"(r0), "=r"(r1), "=r"(r2), "=r"(r3) : "r"(addr))

#define MMA16(c, a, b)                                                                  \
    asm volatile("mma.sync.aligned.m16n8k16.row.col.f32.f16.f16.f32 "                   \
                 "{%0,%1,%2,%3},{%4,%5,%6,%7},{%8,%9},{%0,%1,%2,%3};"                   \
                 : "+f"((c)[0]), "+f"((c)[1]), "+f"((c)[2]), "+f"((c)[3])               \
                 : "r"((a)[0]), "r"((a)[1]), "r"((a)[2]), "r"((a)[3]),                  \
                   "r"((b)[0]), "r"((b)[1]))

__device__ __forceinline__ void ld_tile_p(uint32_t sbase, const uint64_t* __restrict__ rp,
                                          uint32_t koff, int tid) {
    #pragma unroll
    for (int c = tid; c < 1024; c += 256) {
        int row = c >> 3, ch = c & 7;
        const char* gp = (const char*)(rp[row] + koff) + ch * 16;
        uint32_t off = (uint32_t)(row * 128 + ((ch ^ (row & 7)) << 4));
        CPA(sbase + off, gp);
    }
}

// ---------------------------------------------------------------------------
// Router: 2 tokens per warp; weight conversion; fused bucketize. (R12 verbatim)
// ---------------------------------------------------------------------------
__global__ __launch_bounds__(256) void router_kernel(
    const float* __restrict__ x, const float* __restrict__ rw, const float* __restrict__ rb,
    const float* __restrict__ w1, const float* __restrict__ w2)
{
    __shared__ int s_pair[16];
    {
        const int N1 = E_NUM * HD_DIM * C_DIM;
        for (int i = blockIdx.x * 256 + threadIdx.x; i < N1; i += gridDim.x * 256) {
            g_w1h[i] = __float2half_rn(w1[i]);
            g_w2h[i] = __float2half_rn(w2[i]);
        }
    }
    const int warp = threadIdx.x >> 5, lane = threadIdx.x & 31;
    const int t0 = blockIdx.x * 16 + warp * 2;
    const float* xr0 = x + (size_t)t0 * C_DIM;
    const float* xr1 = xr0 + C_DIM;
    __half* xo0 = g_xh + (size_t)t0 * C_DIM;
    __half* xo1 = xo0 + C_DIM;

    float a0[4] = {0.f, 0.f, 0.f, 0.f};
    float a1[4] = {0.f, 0.f, 0.f, 0.f};
    for (int c = lane * 4; c < C_DIM; c += 128) {
        float4 x0 = *(const float4*)(xr0 + c);
        float4 x1 = *(const float4*)(xr1 + c);
        #pragma unroll
        for (int e = 0; e < 4; e++) {
            float4 wv = *(const float4*)(rw + e * C_DIM + c);
            a0[e] += x0.x*wv.x + x0.y*wv.y + x0.z*wv.z + x0.w*wv.w;
            a1[e] += x1.x*wv.x + x1.y*wv.y + x1.z*wv.z + x1.w*wv.w;
        }
        __half2 h0 = __floats2half2_rn(x0.x, x0.y);
        __half2 h1 = __floats2half2_rn(x0.z, x0.w);
        *(uint2*)(xo0 + c) = make_uint2(*(uint32_t*)&h0, *(uint32_t*)&h1);
        __half2 h2 = __floats2half2_rn(x1.x, x1.y);
        __half2 h3 = __floats2half2_rn(x1.z, x1.w);
        *(uint2*)(xo1 + c) = make_uint2(*(uint32_t*)&h2, *(uint32_t*)&h3);
    }
    #pragma unroll
    for (int o = 16; o > 0; o >>= 1) {
        #pragma unroll
        for (int e = 0; e < 4; e++) {
            a0[e] += __shfl_xor_sync(0xffffffffu, a0[e], o);
            a1[e] += __shfl_xor_sync(0xffffffffu, a1[e], o);
        }
    }
    if (lane < 2) {
        const float* av = (lane == 0) ? a0 : a1;
        const int t = t0 + lane;
        float l[4];
        #pragma unroll
        for (int e = 0; e < 4; e++) l[e] = av[e] + rb[e];
        float mx = fmaxf(fmaxf(l[0], l[1]), fmaxf(l[2], l[3]));
        float p[4]; float Z = 0.f;
        #pragma unroll
        for (int e = 0; e < 4; e++) { p[e] = expf(l[e] - mx); Z += p[e]; }
        #pragma unroll
        for (int e = 0; e < 4; e++) p[e] /= Z;
        int i0 = 0;
        #pragma unroll
        for (int e = 1; e < 4; e++) if (p[e] > p[i0]) i0 = e;
        int i1 = (i0 == 0) ? 1 : 0;
        #pragma unroll
        for (int e = 0; e < 4; e++) if (e != i0 && p[e] > p[i1]) i1 = e;
        float s = p[i0] + p[i1] + 1e-8f;
        float ov[4] = {0.f, 0.f, 0.f, 0.f};
        ov[i0] = p[i0] / s; ov[i1] = p[i1] / s;
        ((float4*)g_combine)[t] = make_float4(ov[0], ov[1], ov[2], ov[3]);
        int lo = min(i0, i1), hi = max(i0, i1);
        s_pair[warp * 2 + lane] = (lo == 0) ? hi - 1 : ((lo == 1) ? hi + 1 : 5);
    }
    __syncthreads();
    if (threadIdx.x < 16) {
        int pid = s_pair[threadIdx.x];
        unsigned mask = __match_any_sync(0x0000ffffu, pid) & 0xffffu;
        int leader = __ffs(mask) - 1;
        int rank = __popc(mask & ((1u << threadIdx.x) - 1));
        int base = 0;
        if (threadIdx.x == leader) base = atomicAdd(&g_cnt[pid], __popc(mask));
        base = __shfl_sync(0x0000ffffu, base, leader);
        g_bucket[pid * T_TOK + base + rank] = blockIdx.x * 16 + threadIdx.x;
    }
}

// ---------------------------------------------------------------------------
// Scheduler helpers
// ---------------------------------------------------------------------------
__device__ __forceinline__ void decode_item(int item, const int* s_mt, int tot1,
                                            int* mode, int* b, int* mt, int* nt)
{
    if (item < tot1) {
        *mode = 1;
        int it = item;
        #pragma unroll
        for (int e = 0; e < 6; e++) {
            int n = s_mt[e] * 3;                 // fc1: 3 n-tiles (384/128)
            if (it < n) { *b = e; *mt = it / 3; *nt = it % 3; return; }
            it -= n;
        }
    } else {
        *mode = 2;
        int it = item - tot1;
        #pragma unroll
        for (int e = 0; e < 6; e++) {
            int n = s_mt[e] * 6;                 // fc2: 6 n-tiles (768/128)
            if (it < n) { *b = e; *mt = it / 6; *nt = it % 6; return; }
            it -= n;
        }
    }
    *mode = 0; *b = 0; *mt = 0; *nt = 0;         // unreachable for valid items
}

// runtime-mode table setup into buffer `par`
__device__ __forceinline__ void setup_tables_rt(int mode, int b, int cnt, int m0, int n0,
                                                char* smc, int par)
{
    uint64_t* rpA = (uint64_t*)(smc + TBL_OFF + par * TBL_PAR);
    uint64_t* rpB = rpA + 128;
    int* stok = (int*)(rpB + 128);
    const int e0 = c_pairs[b][0], e1 = c_pairs[b][1];
    const int tid = threadIdx.x;
    if (tid < 128) {
        int p = m0 + tid;
        int t = g_bucket[b * T_TOK + (p < cnt ? p : m0)];
        stok[tid] = t;
        rpA[tid] = (mode == 1)
            ? (uint64_t)(const char*)(g_xh + (size_t)t * C_DIM)
            : (uint64_t)(const char*)(g_hmid + (size_t)t * 384);
    } else {
        int row = tid - 128;
        if (mode == 1) {
            int n = n0 + row;
            int e = (n < HD_DIM) ? e0 : e1;
            int h = (n < HD_DIM) ? n : n - HD_DIM;
            rpB[row] = (uint64_t)(const char*)(g_w1h + ((size_t)e * HD_DIM + h) * C_DIM);
        } else {
            rpB[row] = (uint64_t)(const char*)(g_w2h + (size_t)(n0 + row) * HD_DIM);
        }
    }
}

template <int MODE>
__device__ __forceinline__ uint32_t koffB_f(int i, int b) {
    if (MODE == 1) return (uint32_t)(i * 128);
    int e = i / 3, h0 = (i - e * 3) * KB;
    int ee = (e == 0) ? c_pairs[b][0] : c_pairs[b][1];
    return (uint32_t)(ee * C_DIM * HD_DIM + h0) * 2u;
}

template <int MODE>
__device__ __forceinline__ void issue_stage(int s, int j, int b, char* smc,
                                            uint32_t sb, int par, int tid)
{
    uint64_t* rpA = (uint64_t*)(smc + TBL_OFF + par * TBL_PAR);
    uint64_t* rpB = rpA + 128;
    ld_tile_p(sb + s * STG_B, rpA, (uint32_t)(j * 128), tid);
    ld_tile_p(sb + s * STG_B + 16384, rpB, koffB_f<MODE>(j, b), tid);
}

// ---------------------------------------------------------------------------
// One item: prologue + mainloop (R12-identical data path), then early-grab of
// next item with table setup overlapped against the epilogue.
// Precondition: tables(par) visible (caller barrier), no cp.async outstanding.
// Postcondition: no cp.async outstanding; tables(par^1) written if next valid.
// ---------------------------------------------------------------------------
template <int MODE>
__device__ __forceinline__ void run_item(
    int b, int cnt, int m0, int n0, int par,
    const float* __restrict__ bias, float* __restrict__ outp,
    char* smc, uint32_t sb, int* sh_item,
    const int* s_mt, const int* s_cnt, int tot1, int TOT,
    int* p_nxt, int* p_nmode, int* p_nb, int* p_nmt, int* p_nnt, bool* p_pend)
{
    constexpr int NKI = (MODE == 1) ? (C_DIM / KB) : (384 / KB);   // 12 / 6
    const int tid = threadIdx.x, lane = tid & 31, w = tid >> 5;
    const int wm = w & 1, wn = w >> 1;
    const int lq = lane >> 2, lr = lane & 3;
    const int ph = w & 3;
    const int e0 = c_pairs[b][0], e1 = c_pairs[b][1];

    const int ms = lane >> 3, rl = lane & 7;
    const int a_ms2 = ms >> 1, b_ms1 = ms & 1;
    uint32_t a_rowoff[4], b_rowoff[2];
    #pragma unroll
    for (int mi = 0; mi < 4; mi++)
        a_rowoff[mi] = (uint32_t)((wm * 64 + mi * 16 + (ms & 1) * 8 + rl) * 128);
    #pragma unroll
    for (int p = 0; p < 2; p++)
        b_rowoff[p] = (uint32_t)((wn * 32 + p * 16 + (ms >> 1) * 8 + rl) * 128);

    float acc[4][4][4] = {};

    // prologue: stages 0,1
    issue_stage<MODE>(0, 0, b, smc, sb, par, tid); CPC();
    issue_stage<MODE>(1, 1, b, smc, sb, par, tid); CPC();

    for (int i = 0; i < NKI; i++) {
        if (i < NKI - 1) { CPW(1); } else { CPW(0); }
        __syncthreads();
        if (i + 2 < NKI) {
            issue_stage<MODE>((i + 2) % 3, i + 2, b, smc, sb, par, tid);
            CPC();
        }
        const uint32_t smA = sb + (i % 3) * STG_B;
        const uint32_t smB = smA + 16384;
        #pragma unroll
        for (int kks = 0; kks < 4; kks++) {
            const int kk = (kks + ph) & 3;
            uint32_t a[4][4], bb[4][2];
            const uint32_t koA = (uint32_t)(((2 * kk + a_ms2) ^ rl) << 4);
            const uint32_t koB = (uint32_t)(((2 * kk + b_ms1) ^ rl) << 4);
            #pragma unroll
            for (int mi = 0; mi < 4; mi++)
                LDSM4(a[mi][0], a[mi][1], a[mi][2], a[mi][3], smA + a_rowoff[mi] + koA);
            #pragma unroll
            for (int p = 0; p < 2; p++)
                LDSM4(bb[2*p][0], bb[2*p][1], bb[2*p+1][0], bb[2*p+1][1],
                      smB + b_rowoff[p] + koB);
            #pragma unroll
            for (int mi = 0; mi < 4; mi++)
                #pragma unroll
                for (int nj = 0; nj < 4; nj++)
                    MMA16(acc[mi][nj], a[mi], bb[nj]);
        }
    }
    __syncthreads();                    // stage reads done; safe to reuse smem later

    // ---- early grab + decode + table setup for next item (overlap window) ----
    if (tid == 0) *sh_item = atomicAdd(&g_item, 1);
    __syncthreads();
    const int nxt = *sh_item;
    *p_nxt = nxt;

    int nmode = 0, nb = 0, nmt = 0, nnt = 0;
    bool pend = false;
    if (nxt < TOT) {
        decode_item(nxt, s_mt, tot1, &nmode, &nb, &nmt, &nnt);
        // overlap spin only when current item is fc2 (no pending done-bump held)
        if (nmode == 2) {
            if (MODE == 2) {
                if (tid == 0) {
                    const int need = s_mt[nb] * 3;
                    while (*(volatile int*)&g_done[nb] < need) { }
                }
                pend = false;           // spin completed inside overlap; joined at final barrier
            } else {
                pend = true;            // spin cold at loop top (after our bump)
            }
        }
        setup_tables_rt(nmode, nb, s_cnt[nb], nmt * 128, nnt * 128, smc, par ^ 1);
    }
    *p_nmode = nmode; *p_nb = nb; *p_nmt = nmt; *p_nnt = nnt; *p_pend = pend;

    // ---------------- epilogue (reads tables at par) ----------------
    {
        int* stok = (int*)((uint64_t*)(smc + TBL_OFF + par * TBL_PAR) + 256);
        #pragma unroll
        for (int mi = 0; mi < 4; mi++) {
            #pragma unroll
            for (int half = 0; half < 2; half++) {
                const int rloc = wm * 64 + mi * 16 + lq + half * 8;
                if (m0 + rloc >= cnt) continue;
                const int t = stok[rloc];
                if (MODE == 1) {
                    __half* orow = g_hmid + (size_t)t * 384;
                    #pragma unroll
                    for (int nj = 0; nj < 4; nj++) {
                        const int n = n0 + wn * 32 + nj * 8 + lr * 2;
                        const int e = (n < HD_DIM) ? e0 : e1;
                        const int h = (n < HD_DIM) ? n : n - HD_DIM;
                        const float cw = g_combine[t * 4 + e];
                        float vv[2];
                        #pragma unroll
                        for (int u = 0; u < 2; u++) {
                            float d = acc[mi][nj][half * 2 + u] + __ldg(&bias[e * HD_DIM + h + u]);
                            float g = 0.5f * d * (1.0f + erff(d * 0.70710678118654752f));
                            vv[u] = g * cw;
                        }
                        __half2 hv = __floats2half2_rn(vv[0], vv[1]);
                        *(__half2*)(orow + n) = hv;
                    }
                } else {
                    const float4 cw = ((const float4*)g_combine)[t];
                    float* orow = outp + (size_t)t * C_DIM;
                    #pragma unroll
                    for (int nj = 0; nj < 4; nj++) {
                        const int n = n0 + wn * 32 + nj * 8 + lr * 2;
                        float2 v;
                        #pragma unroll
                        for (int u = 0; u < 2; u++) {
                            const int c = n + u;
                            float bv = cw.x * __ldg(&bias[0 * C_DIM + c])
                                     + cw.y * __ldg(&bias[1 * C_DIM + c])
                                     + cw.z * __ldg(&bias[2 * C_DIM + c])
                                     + cw.w * __ldg(&bias[3 * C_DIM + c]);
                            ((float*)&v)[u] = acc[mi][nj][half * 2 + u] + bv;
                        }
                        *(float2*)(orow + n) = v;
                    }
                }
            }
        }
    }
    __syncthreads();                    // epilogue + overlap spin + tables done
    if (MODE == 1 && tid == 0) {
        __threadfence();
        atomicAdd(&g_done[b], 1);
    }
}

// ---------------------------------------------------------------------------
// Persistent fused scheduler. Self-resetting.
// ---------------------------------------------------------------------------
__global__ __launch_bounds__(256, 2)
void moe_fused(const float* __restrict__ b1, const float* __restrict__ b2,
               float* __restrict__ outp)
{
    extern __shared__ __align__(128) char smc[];
    const uint32_t sb = smem_u32(smc);
    int* s_sch = (int*)(smc + SCH_OFF);   // [0:6) mt, [6:12) cnt, 12 tot1, 13 TOT, 14 item
    const int tid = threadIdx.x;

    if (tid < 6) {
        int c = __ldg(&g_cnt[tid]);
        s_sch[6 + tid] = c;
        s_sch[tid] = (c + 127) >> 7;
    }
    __syncthreads();
    if (tid == 0) {
        int t1 = 0, t2 = 0;
        #pragma unroll
        for (int e = 0; e < 6; e++) { t1 += s_sch[e] * 3; t2 += s_sch[e] * 6; }
        s_sch[12] = t1;
        s_sch[13] = t1 + t2;
        s_sch[14] = atomicAdd(&g_item, 1);
    }
    __syncthreads();
    const int* s_mt  = s_sch;
    const int* s_cnt = s_sch + 6;
    const int tot1 = s_sch[12];
    const int TOT  = s_sch[13];
    int item = s_sch[14];

    int par = 0;
    int mode = 0, b = 0, mt = 0, nt = 0;
    bool pend = false;

    // initial decode + table setup
    if (item < TOT) {
        decode_item(item, s_mt, tot1, &mode, &b, &mt, &nt);
        pend = (mode == 2);
        setup_tables_rt(mode, b, s_cnt[b], mt * 128, nt * 128, smc, par);
    }
    __syncthreads();

    while (item < TOT) {
        if (pend && tid == 0) {
            const int need = s_mt[b] * 3;
            while (*(volatile int*)&g_done[b] < need) { }
        }
        __syncthreads();                // tables(par) visible + spin complete

        int nxt, nmode, nb, nmt, nnt;
        bool npend;
        if (mode == 1)
            run_item<1>(b, s_cnt[b], mt * 128, nt * 128, par, b1, nullptr,
                        smc, sb, s_sch + 14, s_mt, s_cnt, tot1, TOT,
                        &nxt, &nmode, &nb, &nmt, &nnt, &npend);
        else
            run_item<2>(b, s_cnt[b], mt * 128, nt * 128, par, b2, outp,
                        smc, sb, s_sch + 14, s_mt, s_cnt, tot1, TOT,
                        &nxt, &nmode, &nb, &nmt, &nnt, &npend);

        item = nxt; mode = nmode; b = nb; mt = nmt; nt = nnt; pend = npend;
        par ^= 1;
    }

    // self-reset for next graph replay
    if (tid == 0) {
        int f = atomicAdd(&g_fin, 1);
        if (f == (int)gridDim.x - 1) {
            #pragma unroll
            for (int e = 0; e < 8; e++) { g_cnt[e] = 0; g_done[e] = 0; }
            g_item = 0;
            g_fin = 0;
            __threadfence();
        }
    }
}

// ---------------------------------------------------------------------------
extern "C" void kernel_launch(void* const* d_in, const int* in_sizes, int n_in,
                              void* d_out, int out_size)
{
    const float* x  = (const float*)d_in[0];
    const float* rw = (const float*)d_in[1];
    const float* rb = (const float*)d_in[2];
    const float* w1 = (const float*)d_in[3];
    const float* b1 = (const float*)d_in[4];
    const float* w2 = (const float*)d_in[5];
    const float* b2 = (const float*)d_in[6];
    float* out = (float*)d_out;

    static int nsm = 0;
    if (nsm == 0) {
        cudaDeviceGetAttribute(&nsm, cudaDevAttrMultiProcessorCount, 0);
        cudaFuncSetAttribute(moe_fused, cudaFuncAttributeMaxDynamicSharedMemorySize, SMEM_TOT);
    }

    router_kernel<<<T_TOK / 16, 256>>>(x, rw, rb, w1, w2);
    moe_fused<<<2 * nsm, 256, SMEM_TOT>>>(b1, b2, out);
}

// round 16
// speedup vs baseline: 1.1977x; 1.0128x over previous
#include <cuda_runtime.h>
#include <cuda_fp16.h>
#include <math.h>
#include <stdint.h>

#define T_TOK 32768
#define C_DIM 768
#define E_NUM 4
#define HD_DIM 192
#define KB 64                           // 64 halfs per k-iter (128B rows)
#define STG_B 32768                     // bytes per stage: A 16KB + B 16KB
#define TBL_OFF (3 * STG_B)
#define TBL_PAR 2560                    // rpA 1024 + rpB 1024 + stok 512
#define SCH_OFF (TBL_OFF + 2 * TBL_PAR)
#define SMEM_TOT (SCH_OFF + 128)
#define MT_MAX 256                      // max m-tiles per bucket (worst-case skew)

__device__ float  g_combine[T_TOK * E_NUM];
__device__ int    g_cnt[8];
__device__ int    g_item;
__device__ int    g_fin;
__device__ int    g_done_mt[6 * MT_MAX];   // per-(bucket, m-tile) fc1 completion
__device__ int    g_bucket[6 * T_TOK];
__device__ __half g_xh[(size_t)T_TOK * C_DIM];
__device__ __half g_hmid[(size_t)T_TOK * 384];
__device__ __half g_w1h[E_NUM * HD_DIM * C_DIM];
__device__ __half g_w2h[E_NUM * C_DIM * HD_DIM];

__constant__ int c_pairs[6][2] = {{0,1},{0,2},{0,3},{1,2},{1,3},{2,3}};

// ---------------- helpers ----------------
__device__ __forceinline__ uint32_t smem_u32(const void* p) {
    uint32_t a;
    asm("{ .reg .u64 t; cvta.to.shared.u64 t, %1; cvt.u32.u64 %0, t; }" : "=r"(a) : "l"(p));
    return a;
}
#define CPA(s, g)  asm volatile("cp.async.cg.shared.global [%0], [%1], 16;" :: "r"(s), "l"(g))
#define CPC()      asm volatile("cp.async.commit_group;" ::: "memory")
#define CPW(n)     asm volatile("cp.async.wait_group %0;" :: "n"(n) : "memory")

#define LDSM4(r0, r1, r2, r3, addr)                                                     \
    asm volatile("ldmatrix.sync.aligned.m8n8.x4.shared.b16 {%0,%1,%2,%3}, [%4];"        \
                 : "=r"(r0), "=r"(r1), "=r"(r2), "=r"(r3) : "r"(addr))

#define MMA16(c, a, b)                                                                  \
    asm volatile("mma.sync.aligned.m16n8k16.row.col.f32.f16.f16.f32 "                   \
                 "{%0,%1,%2,%3},{%4,%5,%6,%7},{%8,%9},{%0,%1,%2,%3};"                   \
                 : "+f"((c)[0]), "+f"((c)[1]), "+f"((c)[2]), "+f"((c)[3])               \
                 : "r"((a)[0]), "r"((a)[1]), "r"((a)[2]), "r"((a)[3]),                  \
                   "r"((b)[0]), "r"((b)[1]))

__device__ __forceinline__ void ld_tile_p(uint32_t sbase, const uint64_t* __restrict__ rp,
                                          uint32_t koff, int tid) {
    #pragma unroll
    for (int c = tid; c < 1024; c += 256) {
        int row = c >> 3, ch = c & 7;
        const char* gp = (const char*)(rp[row] + koff) + ch * 16;
        uint32_t off = (uint32_t)(row * 128 + ((ch ^ (row & 7)) << 4));
        CPA(sbase + off, gp);
    }
}

// ---------------------------------------------------------------------------
// Router: 2 tokens per warp; weight conversion; fused bucketize.
// ---------------------------------------------------------------------------
__global__ __launch_bounds__(256) void router_kernel(
    const float* __restrict__ x, const float* __restrict__ rw, const float* __restrict__ rb,
    const float* __restrict__ w1, const float* __restrict__ w2)
{
    __shared__ int s_pair[16];
    {
        const int N1 = E_NUM * HD_DIM * C_DIM;
        for (int i = blockIdx.x * 256 + threadIdx.x; i < N1; i += gridDim.x * 256) {
            g_w1h[i] = __float2half_rn(w1[i]);
            g_w2h[i] = __float2half_rn(w2[i]);
        }
    }
    const int warp = threadIdx.x >> 5, lane = threadIdx.x & 31;
    const int t0 = blockIdx.x * 16 + warp * 2;
    const float* xr0 = x + (size_t)t0 * C_DIM;
    const float* xr1 = xr0 + C_DIM;
    __half* xo0 = g_xh + (size_t)t0 * C_DIM;
    __half* xo1 = xo0 + C_DIM;

    float a0[4] = {0.f, 0.f, 0.f, 0.f};
    float a1[4] = {0.f, 0.f, 0.f, 0.f};
    for (int c = lane * 4; c < C_DIM; c += 128) {
        float4 x0 = __ldcs((const float4*)(xr0 + c));
        float4 x1 = __ldcs((const float4*)(xr1 + c));
        #pragma unroll
        for (int e = 0; e < 4; e++) {
            float4 wv = *(const float4*)(rw + e * C_DIM + c);
            a0[e] += x0.x*wv.x + x0.y*wv.y + x0.z*wv.z + x0.w*wv.w;
            a1[e] += x1.x*wv.x + x1.y*wv.y + x1.z*wv.z + x1.w*wv.w;
        }
        __half2 h0 = __floats2half2_rn(x0.x, x0.y);
        __half2 h1 = __floats2half2_rn(x0.z, x0.w);
        *(uint2*)(xo0 + c) = make_uint2(*(uint32_t*)&h0, *(uint32_t*)&h1);
        __half2 h2 = __floats2half2_rn(x1.x, x1.y);
        __half2 h3 = __floats2half2_rn(x1.z, x1.w);
        *(uint2*)(xo1 + c) = make_uint2(*(uint32_t*)&h2, *(uint32_t*)&h3);
    }
    #pragma unroll
    for (int o = 16; o > 0; o >>= 1) {
        #pragma unroll
        for (int e = 0; e < 4; e++) {
            a0[e] += __shfl_xor_sync(0xffffffffu, a0[e], o);
            a1[e] += __shfl_xor_sync(0xffffffffu, a1[e], o);
        }
    }
    if (lane < 2) {
        const float* av = (lane == 0) ? a0 : a1;
        const int t = t0 + lane;
        float l[4];
        #pragma unroll
        for (int e = 0; e < 4; e++) l[e] = av[e] + rb[e];
        float mx = fmaxf(fmaxf(l[0], l[1]), fmaxf(l[2], l[3]));
        float p[4]; float Z = 0.f;
        #pragma unroll
        for (int e = 0; e < 4; e++) { p[e] = expf(l[e] - mx); Z += p[e]; }
        #pragma unroll
        for (int e = 0; e < 4; e++) p[e] /= Z;
        int i0 = 0;
        #pragma unroll
        for (int e = 1; e < 4; e++) if (p[e] > p[i0]) i0 = e;
        int i1 = (i0 == 0) ? 1 : 0;
        #pragma unroll
        for (int e = 0; e < 4; e++) if (e != i0 && p[e] > p[i1]) i1 = e;
        float s = p[i0] + p[i1] + 1e-8f;
        float ov[4] = {0.f, 0.f, 0.f, 0.f};
        ov[i0] = p[i0] / s; ov[i1] = p[i1] / s;
        ((float4*)g_combine)[t] = make_float4(ov[0], ov[1], ov[2], ov[3]);
        int lo = min(i0, i1), hi = max(i0, i1);
        s_pair[warp * 2 + lane] = (lo == 0) ? hi - 1 : ((lo == 1) ? hi + 1 : 5);
    }
    __syncthreads();
    if (threadIdx.x < 16) {
        int pid = s_pair[threadIdx.x];
        unsigned mask = __match_any_sync(0x0000ffffu, pid) & 0xffffu;
        int leader = __ffs(mask) - 1;
        int rank = __popc(mask & ((1u << threadIdx.x) - 1));
        int base = 0;
        if (threadIdx.x == leader) base = atomicAdd(&g_cnt[pid], __popc(mask));
        base = __shfl_sync(0x0000ffffu, base, leader);
        g_bucket[pid * T_TOK + base + rank] = blockIdx.x * 16 + threadIdx.x;
    }
}

// ---------------------------------------------------------------------------
// Scheduler helpers
// ---------------------------------------------------------------------------
__device__ __forceinline__ void decode_item(int item, const int* s_mt, int tot1,
                                            int* mode, int* b, int* mt, int* nt)
{
    if (item < tot1) {
        *mode = 1;
        int it = item;
        #pragma unroll
        for (int e = 0; e < 6; e++) {
            int n = s_mt[e] * 3;                 // fc1: 3 n-tiles (384/128)
            if (it < n) { *b = e; *mt = it / 3; *nt = it % 3; return; }
            it -= n;
        }
    } else {
        *mode = 2;
        int it = item - tot1;
        #pragma unroll
        for (int e = 0; e < 6; e++) {
            int n = s_mt[e] * 6;                 // fc2: 6 n-tiles (768/128)
            if (it < n) { *b = e; *mt = it / 6; *nt = it % 6; return; }
            it -= n;
        }
    }
    *mode = 0; *b = 0; *mt = 0; *nt = 0;
}

__device__ __forceinline__ void setup_tables_rt(int mode, int b, int cnt, int m0, int n0,
                                                char* smc, int par)
{
    uint64_t* rpA = (uint64_t*)(smc + TBL_OFF + par * TBL_PAR);
    uint64_t* rpB = rpA + 128;
    int* stok = (int*)(rpB + 128);
    const int e0 = c_pairs[b][0], e1 = c_pairs[b][1];
    const int tid = threadIdx.x;
    if (tid < 128) {
        int p = m0 + tid;
        int t = g_bucket[b * T_TOK + (p < cnt ? p : m0)];
        stok[tid] = t;
        rpA[tid] = (mode == 1)
            ? (uint64_t)(const char*)(g_xh + (size_t)t * C_DIM)
            : (uint64_t)(const char*)(g_hmid + (size_t)t * 384);
    } else {
        int row = tid - 128;
        if (mode == 1) {
            int n = n0 + row;
            int e = (n < HD_DIM) ? e0 : e1;
            int h = (n < HD_DIM) ? n : n - HD_DIM;
            rpB[row] = (uint64_t)(const char*)(g_w1h + ((size_t)e * HD_DIM + h) * C_DIM);
        } else {
            rpB[row] = (uint64_t)(const char*)(g_w2h + (size_t)(n0 + row) * HD_DIM);
        }
    }
}

template <int MODE>
__device__ __forceinline__ uint32_t koffB_f(int i, int b) {
    if (MODE == 1) return (uint32_t)(i * 128);
    int e = i / 3, h0 = (i - e * 3) * KB;
    int ee = (e == 0) ? c_pairs[b][0] : c_pairs[b][1];
    return (uint32_t)(ee * C_DIM * HD_DIM + h0) * 2u;
}

template <int MODE>
__device__ __forceinline__ void issue_stage(int s, int j, int b, char* smc,
                                            uint32_t sb, int par, int tid)
{
    uint64_t* rpA = (uint64_t*)(smc + TBL_OFF + par * TBL_PAR);
    uint64_t* rpB = rpA + 128;
    ld_tile_p(sb + s * STG_B, rpA, (uint32_t)(j * 128), tid);
    ld_tile_p(sb + s * STG_B + 16384, rpB, koffB_f<MODE>(j, b), tid);
}

// ---------------------------------------------------------------------------
// One item: prologue + mainloop, early-grab + table setup overlapped w/ epilogue.
// fc2 gating is per-(bucket, m-tile): g_done_mt[b*MT_MAX+mt] == 3.
// ---------------------------------------------------------------------------
template <int MODE>
__device__ __forceinline__ void run_item(
    int b, int cnt, int m0, int n0, int par,
    const float* __restrict__ bias, float* __restrict__ outp,
    char* smc, uint32_t sb, int* sh_item,
    const int* s_mt, const int* s_cnt, int tot1, int TOT,
    int* p_nxt, int* p_nmode, int* p_nb, int* p_nmt, int* p_nnt, bool* p_pend)
{
    constexpr int NKI = (MODE == 1) ? (C_DIM / KB) : (384 / KB);   // 12 / 6
    const int tid = threadIdx.x, lane = tid & 31, w = tid >> 5;
    const int wm = w & 1, wn = w >> 1;
    const int lq = lane >> 2, lr = lane & 3;
    const int ph = w & 3;
    const int e0 = c_pairs[b][0], e1 = c_pairs[b][1];

    const int ms = lane >> 3, rl = lane & 7;
    const int a_ms2 = ms >> 1, b_ms1 = ms & 1;
    uint32_t a_rowoff[4], b_rowoff[2];
    #pragma unroll
    for (int mi = 0; mi < 4; mi++)
        a_rowoff[mi] = (uint32_t)((wm * 64 + mi * 16 + (ms & 1) * 8 + rl) * 128);
    #pragma unroll
    for (int p = 0; p < 2; p++)
        b_rowoff[p] = (uint32_t)((wn * 32 + p * 16 + (ms >> 1) * 8 + rl) * 128);

    float acc[4][4][4] = {};

    issue_stage<MODE>(0, 0, b, smc, sb, par, tid); CPC();
    issue_stage<MODE>(1, 1, b, smc, sb, par, tid); CPC();

    for (int i = 0; i < NKI; i++) {
        if (i < NKI - 1) { CPW(1); } else { CPW(0); }
        __syncthreads();
        if (i + 2 < NKI) {
            issue_stage<MODE>((i + 2) % 3, i + 2, b, smc, sb, par, tid);
            CPC();
        }
        const uint32_t smA = sb + (i % 3) * STG_B;
        const uint32_t smB = smA + 16384;
        #pragma unroll
        for (int kks = 0; kks < 4; kks++) {
            const int kk = (kks + ph) & 3;
            uint32_t a[4][4], bb[4][2];
            const uint32_t koA = (uint32_t)(((2 * kk + a_ms2) ^ rl) << 4);
            const uint32_t koB = (uint32_t)(((2 * kk + b_ms1) ^ rl) << 4);
            #pragma unroll
            for (int mi = 0; mi < 4; mi++)
                LDSM4(a[mi][0], a[mi][1], a[mi][2], a[mi][3], smA + a_rowoff[mi] + koA);
            #pragma unroll
            for (int p = 0; p < 2; p++)
                LDSM4(bb[2*p][0], bb[2*p][1], bb[2*p+1][0], bb[2*p+1][1],
                      smB + b_rowoff[p] + koB);
            #pragma unroll
            for (int mi = 0; mi < 4; mi++)
                #pragma unroll
                for (int nj = 0; nj < 4; nj++)
                    MMA16(acc[mi][nj], a[mi], bb[nj]);
        }
    }
    __syncthreads();

    // ---- early grab + decode + table setup for next item (overlap window) ----
    if (tid == 0) *sh_item = atomicAdd(&g_item, 1);
    __syncthreads();
    const int nxt = *sh_item;
    *p_nxt = nxt;

    int nmode = 0, nb = 0, nmt = 0, nnt = 0;
    bool pend = false;
    if (nxt < TOT) {
        decode_item(nxt, s_mt, tot1, &nmode, &nb, &nmt, &nnt);
        if (nmode == 2) {
            if (MODE == 2) {
                if (tid == 0) {
                    while (*(volatile int*)&g_done_mt[nb * MT_MAX + nmt] < 3) { }
                }
                pend = false;
            } else {
                pend = true;            // current fc1 may produce the awaited tile
            }
        }
        setup_tables_rt(nmode, nb, s_cnt[nb], nmt * 128, nnt * 128, smc, par ^ 1);
    }
    *p_nmode = nmode; *p_nb = nb; *p_nmt = nmt; *p_nnt = nnt; *p_pend = pend;

    // ---------------- epilogue (reads tables at par) ----------------
    {
        int* stok = (int*)((uint64_t*)(smc + TBL_OFF + par * TBL_PAR) + 256);
        #pragma unroll
        for (int mi = 0; mi < 4; mi++) {
            #pragma unroll
            for (int half = 0; half < 2; half++) {
                const int rloc = wm * 64 + mi * 16 + lq + half * 8;
                if (m0 + rloc >= cnt) continue;
                const int t = stok[rloc];
                if (MODE == 1) {
                    __half* orow = g_hmid + (size_t)t * 384;
                    #pragma unroll
                    for (int nj = 0; nj < 4; nj++) {
                        const int n = n0 + wn * 32 + nj * 8 + lr * 2;
                        const int e = (n < HD_DIM) ? e0 : e1;
                        const int h = (n < HD_DIM) ? n : n - HD_DIM;
                        const float cw = g_combine[t * 4 + e];
                        float vv[2];
                        #pragma unroll
                        for (int u = 0; u < 2; u++) {
                            float d = acc[mi][nj][half * 2 + u] + __ldg(&bias[e * HD_DIM + h + u]);
                            float g = 0.5f * d * (1.0f + erff(d * 0.70710678118654752f));
                            vv[u] = g * cw;
                        }
                        __half2 hv = __floats2half2_rn(vv[0], vv[1]);
                        *(__half2*)(orow + n) = hv;
                    }
                } else {
                    const float4 cw = ((const float4*)g_combine)[t];
                    float* orow = outp + (size_t)t * C_DIM;
                    #pragma unroll
                    for (int nj = 0; nj < 4; nj++) {
                        const int n = n0 + wn * 32 + nj * 8 + lr * 2;
                        float2 v;
                        #pragma unroll
                        for (int u = 0; u < 2; u++) {
                            const int c = n + u;
                            float bv = cw.x * __ldg(&bias[0 * C_DIM + c])
                                     + cw.y * __ldg(&bias[1 * C_DIM + c])
                                     + cw.z * __ldg(&bias[2 * C_DIM + c])
                                     + cw.w * __ldg(&bias[3 * C_DIM + c]);
                            ((float*)&v)[u] = acc[mi][nj][half * 2 + u] + bv;
                        }
                        *(float2*)(orow + n) = v;
                    }
                }
            }
        }
    }
    __syncthreads();                    // epilogue + overlap work done
    if (MODE == 1 && tid == 0) {
        __threadfence();
        atomicAdd(&g_done_mt[b * MT_MAX + (m0 >> 7)], 1);
    }
}

// ---------------------------------------------------------------------------
// Persistent fused scheduler. Self-resetting (block-parallel reset).
// ---------------------------------------------------------------------------
__global__ __launch_bounds__(256, 2)
void moe_fused(const float* __restrict__ b1, const float* __restrict__ b2,
               float* __restrict__ outp)
{
    extern __shared__ __align__(128) char smc[];
    const uint32_t sb = smem_u32(smc);
    int* s_sch = (int*)(smc + SCH_OFF);   // [0:6) mt, [6:12) cnt, 12 tot1, 13 TOT, 14 item, 15 flag
    const int tid = threadIdx.x;

    if (tid < 6) {
        int c = __ldg(&g_cnt[tid]);
        s_sch[6 + tid] = c;
        s_sch[tid] = (c + 127) >> 7;
    }
    __syncthreads();
    if (tid == 0) {
        int t1 = 0, t2 = 0;
        #pragma unroll
        for (int e = 0; e < 6; e++) { t1 += s_sch[e] * 3; t2 += s_sch[e] * 6; }
        s_sch[12] = t1;
        s_sch[13] = t1 + t2;
        s_sch[14] = atomicAdd(&g_item, 1);
    }
    __syncthreads();
    const int* s_mt  = s_sch;
    const int* s_cnt = s_sch + 6;
    const int tot1 = s_sch[12];
    const int TOT  = s_sch[13];
    int item = s_sch[14];

    int par = 0;
    int mode = 0, b = 0, mt = 0, nt = 0;
    bool pend = false;

    if (item < TOT) {
        decode_item(item, s_mt, tot1, &mode, &b, &mt, &nt);
        pend = (mode == 2);
        setup_tables_rt(mode, b, s_cnt[b], mt * 128, nt * 128, smc, par);
    }
    __syncthreads();

    while (item < TOT) {
        if (pend && tid == 0) {
            while (*(volatile int*)&g_done_mt[b * MT_MAX + mt] < 3) { }
        }
        __syncthreads();                // tables(par) visible + spin complete

        int nxt, nmode, nb, nmt, nnt;
        bool npend;
        if (mode == 1)
            run_item<1>(b, s_cnt[b], mt * 128, nt * 128, par, b1, nullptr,
                        smc, sb, s_sch + 14, s_mt, s_cnt, tot1, TOT,
                        &nxt, &nmode, &nb, &nmt, &nnt, &npend);
        else
            run_item<2>(b, s_cnt[b], mt * 128, nt * 128, par, b2, outp,
                        smc, sb, s_sch + 14, s_mt, s_cnt, tot1, TOT,
                        &nxt, &nmode, &nb, &nmt, &nnt, &npend);

        item = nxt; mode = nmode; b = nb; mt = nmt; nt = nnt; pend = npend;
        par ^= 1;
    }

    // self-reset for next graph replay: last CTA clears all state (block-parallel)
    __syncthreads();
    if (tid == 0) s_sch[15] = (atomicAdd(&g_fin, 1) == (int)gridDim.x - 1) ? 1 : 0;
    __syncthreads();
    if (s_sch[15]) {
        for (int i = tid; i < 6 * MT_MAX; i += 256) g_done_mt[i] = 0;
        if (tid < 8) g_cnt[tid] = 0;
        if (tid == 0) { g_item = 0; g_fin = 0; }
        __threadfence();
    }
}

// ---------------------------------------------------------------------------
extern "C" void kernel_launch(void* const* d_in, const int* in_sizes, int n_in,
                              void* d_out, int out_size)
{
    const float* x  = (const float*)d_in[0];
    const float* rw = (const float*)d_in[1];
    const float* rb = (const float*)d_in[2];
    const float* w1 = (const float*)d_in[3];
    const float* b1 = (const float*)d_in[4];
    const float* w2 = (const float*)d_in[5];
    const float* b2 = (const float*)d_in[6];
    float* out = (float*)d_out;

    static int nsm = 0;
    if (nsm == 0) {
        cudaDeviceGetAttribute(&nsm, cudaDevAttrMultiProcessorCount, 0);
        cudaFuncSetAttribute(moe_fused, cudaFuncAttributeMaxDynamicSharedMemorySize, SMEM_TOT);
    }

    router_kernel<<<T_TOK / 16, 256>>>(x, rw, rb, w1, w2);
    moe_fused<<<2 * nsm, 256, SMEM_TOT>>>(b1, b2, out);
}